// round 13
// baseline (speedup 1.0000x reference)
#include <cuda_runtime.h>
#include <stdint.h>
#include <math.h>

#define BSZ 4
#define TSEQ 2048
#define CDIM 1024
#define HN 16
#define DH 64

// __device__ scratch (allocation-free rule)
__device__ float g_q[(size_t)BSZ * HN * TSEQ * DH];    // (B,H,T,D)
__device__ float g_att[(size_t)BSZ * TSEQ * CDIM];     // (B,T,C), k-permuted + rounded
__device__ float g_wt[4][(size_t)CDIM * CDIM];         // W^T, k-permuted + rounded
__device__ float g_vt[(size_t)BSZ * HN * DH * TSEQ];   // V^T (B,H,D,T), rounded
__device__ float g_xp[(size_t)BSZ * TSEQ * CDIM];      // x, k-permuted + rounded

__device__ __forceinline__ float to_tf32(float x) {
    float r; asm("cvt.rna.tf32.f32 %0, %1;" : "=f"(r) : "f"(x)); return r;
}

__device__ __forceinline__ void mma_tf32(float* d, const float* a, const float* b) {
    asm("mma.sync.aligned.m16n8k8.row.col.f32.tf32.tf32.f32 "
        "{%0,%1,%2,%3}, {%4,%5,%6,%7}, {%8,%9}, {%0,%1,%2,%3};"
        : "+f"(d[0]), "+f"(d[1]), "+f"(d[2]), "+f"(d[3])
        : "f"(a[0]), "f"(a[1]), "f"(a[2]), "f"(a[3]), "f"(b[0]), "f"(b[1]));
}

// permuted position of col k within its 8-group (pos 2j -> k=j, 2j+1 -> k=j+4)
__device__ __forceinline__ int kperm(int k) {
    return (k & ~7) + ((k & 3) * 2) + ((k & 4) ? 1 : 0);
}

__device__ __forceinline__ void cp_async16(uint32_t sdst, const void* gsrc) {
    asm volatile("cp.async.cg.shared.global [%0], [%1], 16;"
                 :: "r"(sdst), "l"(gsrc) : "memory");
}

// ---------------------------------------------------------------------------
// x -> g_xp: tf32 round + k-permute (per 8-group)
// ---------------------------------------------------------------------------
__global__ void perm_x(const float* __restrict__ x) {
    const int m = blockIdx.x;
    const float* src = x + (size_t)m * CDIM;
    float* dst = (float*)g_xp + (size_t)m * CDIM;
    for (int k = threadIdx.x; k < CDIM; k += 256)
        dst[kperm(k)] = to_tf32(src[k]);
}

// ---------------------------------------------------------------------------
// weight transpose + round + k-permute: g_wt[z][n][perm(k)] = rna(w_z[k][n])
// ---------------------------------------------------------------------------
__global__ void transpose_w(const float* __restrict__ w0, const float* __restrict__ w1,
                            const float* __restrict__ w2, const float* __restrict__ w3) {
    __shared__ float t[32][33];
    const float* src = (blockIdx.z == 0) ? w0 : (blockIdx.z == 1) ? w1
                     : (blockIdx.z == 2) ? w2 : w3;
    float* dst = g_wt[blockIdx.z];
    const int n0 = blockIdx.x * 32, k0 = blockIdx.y * 32;
    const int x = threadIdx.x, y = threadIdx.y;
#pragma unroll
    for (int i = 0; i < 32; i += 8)
        t[y + i][x] = src[(size_t)(k0 + y + i) * CDIM + n0 + x];
    __syncthreads();
    const int kp = kperm(k0 + x);
#pragma unroll
    for (int i = 0; i < 32; i += 8)
        dst[(size_t)(n0 + y + i) * CDIM + kp] = to_tf32(t[x][y + i]);
}

// ---------------------------------------------------------------------------
// V transpose + tf32 rounding: g_vt[bh][d][t] = rna(vout[bh][t][d])
// ---------------------------------------------------------------------------
__global__ void transpose_v(const float* __restrict__ v) {
    __shared__ float t[32][33];
    const int bh = blockIdx.z;
    const int t0 = blockIdx.x * 32, d0 = blockIdx.y * 32;
    const int x = threadIdx.x, y = threadIdx.y;
    const float* src = v + (size_t)bh * TSEQ * DH;
    float* dst = (float*)g_vt + (size_t)bh * DH * TSEQ;
#pragma unroll
    for (int i = 0; i < 32; i += 8)
        t[y + i][x] = src[(size_t)(t0 + y + i) * DH + d0 + x];
    __syncthreads();
#pragma unroll
    for (int i = 0; i < 32; i += 8)
        dst[(size_t)(d0 + y + i) * TSEQ + t0 + x] = to_tf32(t[x][y + i]);
}

// ---------------------------------------------------------------------------
// cp.async double-buffered tf32 GEMM: out = A @ W + bias
// Block 128x128, BK=16 x 2 stages, 128 threads (4 warps, warp = 64x64).
// A and W are pre-rounded AND pre-k-permuted in gmem, so cp.async 16B chunks
// land directly in the mma-ready smem image. Pad 20 floats/row (16B aligned,
// bank-cycling for fragment LDS.64).
// IN_MODE 1: A = g_att, else A = g_xp
// OUT_MODE 0: row-major out  1: (B,H,T,D) out  2: (B,H,T,D) into g_q
// ---------------------------------------------------------------------------
template <int IN_MODE, int OUT_MODE>
__global__ __launch_bounds__(128, 2)
void gemm_cp(const float* __restrict__ bias, float* __restrict__ outp, int wsel) {
    const float* A = (IN_MODE == 1) ? (const float*)g_att : (const float*)g_xp;
    const float* Wt = g_wt[wsel];
    float* out = (OUT_MODE == 2) ? (float*)g_q : outp;

    __shared__ float smA[2][128][20];
    __shared__ float smB[2][128][20];
    __shared__ float smBias[128];

    const int tid = threadIdx.x;
    const int lane = tid & 31;
    const int wid = tid >> 5;
    const int warp_m = wid >> 1;     // 0..1 (x64 rows)
    const int warp_n = wid & 1;      // 0..1 (x64 cols)
    const int g = lane >> 2;         // 0..7
    const int c = lane & 3;          // 0..3
    const int m0 = blockIdx.y * 128;
    const int n0 = blockIdx.x * 128;

    smBias[tid] = bias[n0 + tid];

    const uint32_t sA = (uint32_t)__cvta_generic_to_shared(&smA[0][0][0]);
    const uint32_t sB = (uint32_t)__cvta_generic_to_shared(&smB[0][0][0]);
    const uint32_t stage_bytes = 128 * 20 * 4;

    // per-thread chunk coords: 4 chunks per operand per stage
    // cid = tid + it*128; r = cid>>2; off = (cid&3)*4  (floats within 16-group)
    float acc[4][8][4];
#pragma unroll
    for (int mt = 0; mt < 4; mt++)
#pragma unroll
        for (int nt = 0; nt < 8; nt++)
#pragma unroll
            for (int i = 0; i < 4; i++) acc[mt][nt][i] = 0.0f;

#define ISSUE_STAGE(st, kt)                                                       \
    do {                                                                          \
        _Pragma("unroll")                                                         \
        for (int it = 0; it < 4; it++) {                                          \
            int cid = tid + it * 128;                                             \
            int r = cid >> 2;                                                     \
            int off = (cid & 3) * 4;                                              \
            cp_async16(sA + (st) * stage_bytes + (r * 20 + off) * 4,              \
                       A + (size_t)(m0 + r) * CDIM + (kt) * 16 + off);            \
            cp_async16(sB + (st) * stage_bytes + (r * 20 + off) * 4,              \
                       Wt + (size_t)(n0 + r) * CDIM + (kt) * 16 + off);           \
        }                                                                         \
        asm volatile("cp.async.commit_group;" ::: "memory");                      \
    } while (0)

    ISSUE_STAGE(0, 0);

    for (int kt = 0; kt < 64; kt++) {
        const int st = kt & 1;
        if (kt + 1 < 64) {
            ISSUE_STAGE(st ^ 1, kt + 1);
            asm volatile("cp.async.wait_group 1;" ::: "memory");
        } else {
            asm volatile("cp.async.wait_group 0;" ::: "memory");
        }
        __syncthreads();

#pragma unroll
        for (int ks = 0; ks < 2; ks++) {
            float afr[4][4];
#pragma unroll
            for (int mt = 0; mt < 4; mt++) {
                int r0 = warp_m * 64 + mt * 16 + g;
                float2 A0 = *(float2*)&smA[st][r0][ks * 8 + 2 * c];
                float2 A1 = *(float2*)&smA[st][r0 + 8][ks * 8 + 2 * c];
                afr[mt][0] = A0.x; afr[mt][1] = A1.x;
                afr[mt][2] = A0.y; afr[mt][3] = A1.y;
            }
            float bfr[8][2];
#pragma unroll
            for (int nt = 0; nt < 8; nt++) {
                int n = warp_n * 64 + nt * 8 + g;
                float2 B0 = *(float2*)&smB[st][n][ks * 8 + 2 * c];
                bfr[nt][0] = B0.x; bfr[nt][1] = B0.y;
            }
#pragma unroll
            for (int mt = 0; mt < 4; mt++)
#pragma unroll
                for (int nt = 0; nt < 8; nt++)
                    mma_tf32(acc[mt][nt], afr[mt], bfr[nt]);
        }
        __syncthreads();
    }
#undef ISSUE_STAGE

#pragma unroll
    for (int mt = 0; mt < 4; mt++) {
        const int row0 = m0 + warp_m * 64 + mt * 16 + g;
#pragma unroll
        for (int nt = 0; nt < 8; nt++) {
            const int cl = warp_n * 64 + nt * 8 + 2 * c;
            const int nb = n0 + cl;
            float2 v0 = make_float2(acc[mt][nt][0] + smBias[cl],
                                    acc[mt][nt][1] + smBias[cl + 1]);
            float2 v1 = make_float2(acc[mt][nt][2] + smBias[cl],
                                    acc[mt][nt][3] + smBias[cl + 1]);
            if (OUT_MODE == 0) {
                *(float2*)(out + (size_t)row0 * CDIM + nb) = v0;
                *(float2*)(out + (size_t)(row0 + 8) * CDIM + nb) = v1;
            } else {
                const int h = nb >> 6, d0 = nb & 63;
                const int b0 = row0 >> 11, t0 = row0 & 2047;
                const int b1 = (row0 + 8) >> 11, t1 = (row0 + 8) & 2047;
                *(float2*)(out + (((size_t)(b0 * HN + h) * TSEQ + t0) * DH + d0)) = v0;
                *(float2*)(out + (((size_t)(b1 * HN + h) * TSEQ + t1) * DH + d0)) = v1;
            }
        }
    }
}

// ---------------------------------------------------------------------------
// Tensor-core causal flash attention (tf32 mma.sync).
// Unchanged mainloop; epilogue now writes g_att k-permuted + rounded
// (consumed by the cp.async proj GEMM).
// ---------------------------------------------------------------------------
__global__ __launch_bounds__(256, 2) void attn_tc(const float* __restrict__ kglob) {
    const float* qg = (const float*)g_q;
    const float* vtg = (const float*)g_vt;
    float* yo = (float*)g_att;

    __shared__ float Ks[32][68];       // [key][d-permuted]
    __shared__ float Vts[64][36];      // [d][key-permuted]
    __shared__ float Ps[8][16][36];    // per-warp P staging

    const int tid = threadIdx.x;
    const int lane = tid & 31;
    const int w = tid >> 5;
    const int g = lane >> 2;
    const int c = lane & 3;

    const int iq = gridDim.x - 1 - blockIdx.x;
    const int bh = blockIdx.y;
    const int row0 = iq * 128 + w * 16;
    const int rg = row0 + g;
    const int rg8 = rg + 8;

    const float* qb = qg + (size_t)bh * TSEQ * DH;
    const float* kb = kglob + (size_t)bh * TSEQ * DH;
    const float* vtb = vtg + (size_t)bh * DH * TSEQ;

    float qf[8][4];
#pragma unroll
    for (int kk = 0; kk < 8; kk++) {
        qf[kk][0] = to_tf32(qb[(size_t)rg * DH + kk * 8 + c] * 0.125f);
        qf[kk][1] = to_tf32(qb[(size_t)rg8 * DH + kk * 8 + c] * 0.125f);
        qf[kk][2] = to_tf32(qb[(size_t)rg * DH + kk * 8 + c + 4] * 0.125f);
        qf[kk][3] = to_tf32(qb[(size_t)rg8 * DH + kk * 8 + c + 4] * 0.125f);
    }

    float o[8][4];
#pragma unroll
    for (int nt = 0; nt < 8; nt++)
#pragma unroll
        for (int i = 0; i < 4; i++) o[nt][i] = 0.0f;
    float m0 = -1e30f, m1 = -1e30f, l0 = 0.0f, l1 = 0.0f;

    const int ntiles = 4 * iq + 4;
    for (int j = 0; j < ntiles; j++) {
        __syncthreads();
#pragma unroll
        for (int it = 0; it < 2; it++) {
            int idx = tid + it * 256;
            int r = idx >> 4, c4 = (idx & 15) * 4;
            float4 a = *(const float4*)(kb + (size_t)(j * 32 + r) * DH + c4);
            int kbase = (c4 & ~7) + ((c4 & 4) ? 1 : 0);
            Ks[r][kbase + 0] = to_tf32(a.x);
            Ks[r][kbase + 2] = to_tf32(a.y);
            Ks[r][kbase + 4] = to_tf32(a.z);
            Ks[r][kbase + 6] = to_tf32(a.w);
            int d = idx >> 3, k4 = (idx & 7) * 4;
            float4 b = *(const float4*)(vtb + (size_t)d * TSEQ + j * 32 + k4);
            int vbase = (k4 & ~7) + ((k4 & 4) ? 1 : 0);
            Vts[d][vbase + 0] = b.x;
            Vts[d][vbase + 2] = b.y;
            Vts[d][vbase + 4] = b.z;
            Vts[d][vbase + 6] = b.w;
        }
        __syncthreads();
        if (j * 32 > row0 + 15) continue;

        float s[4][4];
#pragma unroll
        for (int nt = 0; nt < 4; nt++)
#pragma unroll
            for (int i = 0; i < 4; i++) s[nt][i] = 0.0f;
#pragma unroll
        for (int kk = 0; kk < 8; kk++) {
#pragma unroll
            for (int nt = 0; nt < 4; nt++) {
                float2 bfr = *(float2*)&Ks[nt * 8 + g][kk * 8 + 2 * c];
                mma_tf32(s[nt], qf[kk], (const float*)&bfr);
            }
        }

        if (j >= 4 * iq) {
#pragma unroll
            for (int nt = 0; nt < 4; nt++) {
                int kg = j * 32 + nt * 8 + 2 * c;
                if (kg > rg)      s[nt][0] = -1e30f;
                if (kg + 1 > rg)  s[nt][1] = -1e30f;
                if (kg > rg8)     s[nt][2] = -1e30f;
                if (kg + 1 > rg8) s[nt][3] = -1e30f;
            }
        }

        float t0 = fmaxf(s[0][0], s[0][1]);
        float t1 = fmaxf(s[0][2], s[0][3]);
#pragma unroll
        for (int nt = 1; nt < 4; nt++) {
            t0 = fmaxf(t0, fmaxf(s[nt][0], s[nt][1]));
            t1 = fmaxf(t1, fmaxf(s[nt][2], s[nt][3]));
        }
        t0 = fmaxf(t0, __shfl_xor_sync(0xffffffffu, t0, 1));
        t0 = fmaxf(t0, __shfl_xor_sync(0xffffffffu, t0, 2));
        t1 = fmaxf(t1, __shfl_xor_sync(0xffffffffu, t1, 1));
        t1 = fmaxf(t1, __shfl_xor_sync(0xffffffffu, t1, 2));

        float mn0 = fmaxf(m0, t0), mn1 = fmaxf(m1, t1);
        float a0 = __expf(m0 - mn0), a1 = __expf(m1 - mn1);
        m0 = mn0; m1 = mn1;

        float rs0 = 0.0f, rs1 = 0.0f;
#pragma unroll
        for (int nt = 0; nt < 4; nt++) {
            s[nt][0] = __expf(s[nt][0] - m0);
            s[nt][1] = __expf(s[nt][1] - m0);
            s[nt][2] = __expf(s[nt][2] - m1);
            s[nt][3] = __expf(s[nt][3] - m1);
            rs0 += s[nt][0] + s[nt][1];
            rs1 += s[nt][2] + s[nt][3];
        }
        rs0 += __shfl_xor_sync(0xffffffffu, rs0, 1);
        rs0 += __shfl_xor_sync(0xffffffffu, rs0, 2);
        rs1 += __shfl_xor_sync(0xffffffffu, rs1, 1);
        rs1 += __shfl_xor_sync(0xffffffffu, rs1, 2);
        l0 = l0 * a0 + rs0;
        l1 = l1 * a1 + rs1;

#pragma unroll
        for (int nt = 0; nt < 8; nt++) {
            o[nt][0] *= a0; o[nt][1] *= a0;
            o[nt][2] *= a1; o[nt][3] *= a1;
        }

#pragma unroll
        for (int nt = 0; nt < 4; nt++) {
            *(float2*)&Ps[w][g][nt * 8 + 2 * c] =
                make_float2(to_tf32(s[nt][0]), to_tf32(s[nt][1]));
            *(float2*)&Ps[w][g + 8][nt * 8 + 2 * c] =
                make_float2(to_tf32(s[nt][2]), to_tf32(s[nt][3]));
        }
        __syncwarp();

#pragma unroll
        for (int kk = 0; kk < 4; kk++) {
            float af[4];
            af[0] = Ps[w][g][kk * 8 + c];
            af[1] = Ps[w][g + 8][kk * 8 + c];
            af[2] = Ps[w][g][kk * 8 + c + 4];
            af[3] = Ps[w][g + 8][kk * 8 + c + 4];
#pragma unroll
            for (int nt = 0; nt < 8; nt++) {
                float2 bfr = *(float2*)&Vts[nt * 8 + g][kk * 8 + 2 * c];
                mma_tf32(o[nt], af, (const float*)&bfr);
            }
        }
        __syncwarp();
    }

    // normalize + write to (B,T,C), k-permuted + rounded for the proj GEMM
    const int b = bh >> 4, h = bh & 15;
    const float i0 = 1.0f / l0, i1 = 1.0f / l1;
    float* y0 = yo + ((size_t)(b * TSEQ + rg) * CDIM + h * 64);
    float* y1 = yo + ((size_t)(b * TSEQ + rg8) * CDIM + h * 64);
    const int p0 = ((2 * c) & 3) * 2 + (((2 * c) & 4) ? 1 : 0);
    const int p1 = ((2 * c + 1) & 3) * 2 + (((2 * c + 1) & 4) ? 1 : 0);
#pragma unroll
    for (int nt = 0; nt < 8; nt++) {
        int base = nt * 8;
        y0[base + p0] = to_tf32(o[nt][0] * i0);
        y0[base + p1] = to_tf32(o[nt][1] * i0);
        y1[base + p0] = to_tf32(o[nt][2] * i1);
        y1[base + p1] = to_tf32(o[nt][3] * i1);
    }
}

// ---------------------------------------------------------------------------
extern "C" void kernel_launch(void* const* d_in, const int* in_sizes, int n_in,
                              void* d_out, int out_size) {
    const float* x  = (const float*)d_in[0];
    const float* wq = (const float*)d_in[1];
    const float* bq = (const float*)d_in[2];
    const float* wk = (const float*)d_in[3];
    const float* bk = (const float*)d_in[4];
    const float* wv = (const float*)d_in[5];
    const float* bv = (const float*)d_in[6];
    const float* wp = (const float*)d_in[7];
    const float* bp = (const float*)d_in[8];

    float* out  = (float*)d_out;
    float* kout = out + (size_t)BSZ * TSEQ * CDIM;       // present[0] (k)
    float* vout = kout + (size_t)BSZ * HN * TSEQ * DH;   // present[1] (v)

    perm_x<<<BSZ * TSEQ, 256>>>(x);
    transpose_w<<<dim3(32, 32, 4), dim3(32, 8)>>>(wq, wk, wv, wp);

    dim3 gg(8, 64);   // N/128, M/128
    gemm_cp<0, 2><<<gg, 128>>>(bq, nullptr, 0);   // q -> g_q
    gemm_cp<0, 1><<<gg, 128>>>(bk, kout, 1);      // k -> present[0]
    gemm_cp<0, 1><<<gg, 128>>>(bv, vout, 2);      // v -> present[1]

    transpose_v<<<dim3(TSEQ / 32, DH / 32, BSZ * HN), dim3(32, 8)>>>(vout);

    attn_tc<<<dim3(TSEQ / 128, BSZ * HN), 256>>>(kout);

    gemm_cp<1, 0><<<gg, 128>>>(bp, out, 3);       // y = att @ wp + bp
}

// round 14
// speedup vs baseline: 1.0120x; 1.0120x over previous
#include <cuda_runtime.h>
#include <stdint.h>
#include <math.h>

#define BSZ 4
#define TSEQ 2048
#define CDIM 1024
#define HN 16
#define DH 64

// __device__ scratch (allocation-free rule)
__device__ float g_q[(size_t)BSZ * HN * TSEQ * DH];    // (B,H,T,D)
__device__ float g_att[(size_t)BSZ * TSEQ * CDIM];     // (B,T,C), k-permuted + rounded
__device__ float g_wt[4][(size_t)CDIM * CDIM];         // W^T, k-permuted + rounded
__device__ float g_vt[(size_t)BSZ * HN * DH * TSEQ];   // V^T (B,H,D,T), rounded
__device__ float g_xp[(size_t)BSZ * TSEQ * CDIM];      // x, k-permuted + rounded

__device__ __forceinline__ float to_tf32(float x) {
    float r; asm("cvt.rna.tf32.f32 %0, %1;" : "=f"(r) : "f"(x)); return r;
}

__device__ __forceinline__ void mma_tf32(float* d, const float* a, const float* b) {
    asm("mma.sync.aligned.m16n8k8.row.col.f32.tf32.tf32.f32 "
        "{%0,%1,%2,%3}, {%4,%5,%6,%7}, {%8,%9}, {%0,%1,%2,%3};"
        : "+f"(d[0]), "+f"(d[1]), "+f"(d[2]), "+f"(d[3])
        : "f"(a[0]), "f"(a[1]), "f"(a[2]), "f"(a[3]), "f"(b[0]), "f"(b[1]));
}

// permuted position of col k within its 8-group (pos 2j -> k=j, 2j+1 -> k=j+4)
__device__ __forceinline__ int kperm(int k) {
    return (k & ~7) + ((k & 3) * 2) + ((k & 4) ? 1 : 0);
}

__device__ __forceinline__ void cp_async16(uint32_t sdst, const void* gsrc) {
    asm volatile("cp.async.cg.shared.global [%0], [%1], 16;"
                 :: "r"(sdst), "l"(gsrc) : "memory");
}

// ---------------------------------------------------------------------------
// x -> g_xp: tf32 round + k-permute (per 8-group)
// ---------------------------------------------------------------------------
__global__ void perm_x(const float* __restrict__ x) {
    const int m = blockIdx.x;
    const float* src = x + (size_t)m * CDIM;
    float* dst = (float*)g_xp + (size_t)m * CDIM;
    for (int k = threadIdx.x; k < CDIM; k += 256)
        dst[kperm(k)] = to_tf32(src[k]);
}

// ---------------------------------------------------------------------------
// weight transpose + round + k-permute: g_wt[z][n][perm(k)] = rna(w_z[k][n])
// ---------------------------------------------------------------------------
__global__ void transpose_w(const float* __restrict__ w0, const float* __restrict__ w1,
                            const float* __restrict__ w2, const float* __restrict__ w3) {
    __shared__ float t[32][33];
    const float* src = (blockIdx.z == 0) ? w0 : (blockIdx.z == 1) ? w1
                     : (blockIdx.z == 2) ? w2 : w3;
    float* dst = g_wt[blockIdx.z];
    const int n0 = blockIdx.x * 32, k0 = blockIdx.y * 32;
    const int x = threadIdx.x, y = threadIdx.y;
#pragma unroll
    for (int i = 0; i < 32; i += 8)
        t[y + i][x] = src[(size_t)(k0 + y + i) * CDIM + n0 + x];
    __syncthreads();
    const int kp = kperm(k0 + x);
#pragma unroll
    for (int i = 0; i < 32; i += 8)
        dst[(size_t)(n0 + y + i) * CDIM + kp] = to_tf32(t[x][y + i]);
}

// ---------------------------------------------------------------------------
// V transpose + tf32 rounding: g_vt[bh][d][t] = rna(vout[bh][t][d])
// ---------------------------------------------------------------------------
__global__ void transpose_v(const float* __restrict__ v) {
    __shared__ float t[32][33];
    const int bh = blockIdx.z;
    const int t0 = blockIdx.x * 32, d0 = blockIdx.y * 32;
    const int x = threadIdx.x, y = threadIdx.y;
    const float* src = v + (size_t)bh * TSEQ * DH;
    float* dst = (float*)g_vt + (size_t)bh * DH * TSEQ;
#pragma unroll
    for (int i = 0; i < 32; i += 8)
        t[y + i][x] = src[(size_t)(t0 + y + i) * DH + d0 + x];
    __syncthreads();
#pragma unroll
    for (int i = 0; i < 32; i += 8)
        dst[(size_t)(d0 + y + i) * TSEQ + t0 + x] = to_tf32(t[x][y + i]);
}

// ---------------------------------------------------------------------------
// cp.async double-buffered tf32 GEMM: out = A @ W + bias
// Block 64x128, BK=16 x 2 stages, 128 threads (4 warps 2x2, warp = 32x64).
// acc = 64 regs/thread -> 4 CTAs/SM (16 warps). Single __syncthreads per
// k-iteration: wait_group 0 -> sync -> issue next -> compute.
// A, W pre-rounded + pre-k-permuted in gmem (cp.async lands mma-ready).
// IN_MODE 1: A = g_att, else A = g_xp
// OUT_MODE 0: row-major out  1: (B,H,T,D) out  2: (B,H,T,D) into g_q
// ---------------------------------------------------------------------------
template <int IN_MODE, int OUT_MODE>
__global__ __launch_bounds__(128, 4)
void gemm_cp(const float* __restrict__ bias, float* __restrict__ outp, int wsel) {
    const float* A = (IN_MODE == 1) ? (const float*)g_att : (const float*)g_xp;
    const float* Wt = g_wt[wsel];
    float* out = (OUT_MODE == 2) ? (float*)g_q : outp;

    __shared__ float smA[2][64][20];
    __shared__ float smB[2][128][20];
    __shared__ float smBias[128];

    const int tid = threadIdx.x;
    const int lane = tid & 31;
    const int wid = tid >> 5;
    const int warp_m = wid >> 1;     // 0..1 (x32 rows)
    const int warp_n = wid & 1;      // 0..1 (x64 cols)
    const int g = lane >> 2;         // 0..7
    const int c = lane & 3;          // 0..3
    const int m0 = blockIdx.y * 64;
    const int n0 = blockIdx.x * 128;

    smBias[tid] = bias[n0 + tid];

    const uint32_t sA = (uint32_t)__cvta_generic_to_shared(&smA[0][0][0]);
    const uint32_t sB = (uint32_t)__cvta_generic_to_shared(&smB[0][0][0]);
    const uint32_t stageA = 64 * 20 * 4;
    const uint32_t stageB = 128 * 20 * 4;

    float acc[2][8][4];
#pragma unroll
    for (int mt = 0; mt < 2; mt++)
#pragma unroll
        for (int nt = 0; nt < 8; nt++)
#pragma unroll
            for (int i = 0; i < 4; i++) acc[mt][nt][i] = 0.0f;

#define ISSUE_STAGE(st, kt)                                                       \
    do {                                                                          \
        _Pragma("unroll")                                                         \
        for (int it = 0; it < 2; it++) {   /* A: 256 chunks */                    \
            int ca = tid + it * 128;                                              \
            int r = ca >> 2;                                                      \
            int off = (ca & 3) * 4;                                               \
            cp_async16(sA + (st) * stageA + (r * 20 + off) * 4,                   \
                       A + (size_t)(m0 + r) * CDIM + (kt) * 16 + off);            \
        }                                                                         \
        _Pragma("unroll")                                                         \
        for (int it = 0; it < 4; it++) {   /* B: 512 chunks */                    \
            int cb = tid + it * 128;                                              \
            int r = cb >> 2;                                                      \
            int off = (cb & 3) * 4;                                               \
            cp_async16(sB + (st) * stageB + (r * 20 + off) * 4,                   \
                       Wt + (size_t)(n0 + r) * CDIM + (kt) * 16 + off);           \
        }                                                                         \
        asm volatile("cp.async.commit_group;" ::: "memory");                      \
    } while (0)

    ISSUE_STAGE(0, 0);

    for (int kt = 0; kt < 64; kt++) {
        const int st = kt & 1;
        asm volatile("cp.async.wait_group 0;" ::: "memory");
        __syncthreads();   // stage st visible to all; st^1 free (consumed @ kt-1)
        if (kt + 1 < 64) ISSUE_STAGE(st ^ 1, kt + 1);

#pragma unroll
        for (int ks = 0; ks < 2; ks++) {
            float afr[2][4];
#pragma unroll
            for (int mt = 0; mt < 2; mt++) {
                int r0 = warp_m * 32 + mt * 16 + g;
                float2 A0 = *(float2*)&smA[st][r0][ks * 8 + 2 * c];
                float2 A1 = *(float2*)&smA[st][r0 + 8][ks * 8 + 2 * c];
                afr[mt][0] = A0.x; afr[mt][1] = A1.x;
                afr[mt][2] = A0.y; afr[mt][3] = A1.y;
            }
            float bfr[8][2];
#pragma unroll
            for (int nt = 0; nt < 8; nt++) {
                int n = warp_n * 64 + nt * 8 + g;
                float2 B0 = *(float2*)&smB[st][n][ks * 8 + 2 * c];
                bfr[nt][0] = B0.x; bfr[nt][1] = B0.y;
            }
#pragma unroll
            for (int mt = 0; mt < 2; mt++)
#pragma unroll
                for (int nt = 0; nt < 8; nt++)
                    mma_tf32(acc[mt][nt], afr[mt], bfr[nt]);
        }
    }
#undef ISSUE_STAGE

#pragma unroll
    for (int mt = 0; mt < 2; mt++) {
        const int row0 = m0 + warp_m * 32 + mt * 16 + g;
#pragma unroll
        for (int nt = 0; nt < 8; nt++) {
            const int cl = warp_n * 64 + nt * 8 + 2 * c;
            const int nb = n0 + cl;
            float2 v0 = make_float2(acc[mt][nt][0] + smBias[cl],
                                    acc[mt][nt][1] + smBias[cl + 1]);
            float2 v1 = make_float2(acc[mt][nt][2] + smBias[cl],
                                    acc[mt][nt][3] + smBias[cl + 1]);
            if (OUT_MODE == 0) {
                *(float2*)(out + (size_t)row0 * CDIM + nb) = v0;
                *(float2*)(out + (size_t)(row0 + 8) * CDIM + nb) = v1;
            } else {
                const int h = nb >> 6, d0 = nb & 63;
                const int b0 = row0 >> 11, t0 = row0 & 2047;
                const int b1 = (row0 + 8) >> 11, t1 = (row0 + 8) & 2047;
                *(float2*)(out + (((size_t)(b0 * HN + h) * TSEQ + t0) * DH + d0)) = v0;
                *(float2*)(out + (((size_t)(b1 * HN + h) * TSEQ + t1) * DH + d0)) = v1;
            }
        }
    }
}

// ---------------------------------------------------------------------------
// Tensor-core causal flash attention (tf32 mma.sync) — unchanged from R13.
// Epilogue writes g_att k-permuted + rounded for the proj GEMM.
// ---------------------------------------------------------------------------
__global__ __launch_bounds__(256, 2) void attn_tc(const float* __restrict__ kglob) {
    const float* qg = (const float*)g_q;
    const float* vtg = (const float*)g_vt;
    float* yo = (float*)g_att;

    __shared__ float Ks[32][68];       // [key][d-permuted]
    __shared__ float Vts[64][36];      // [d][key-permuted]
    __shared__ float Ps[8][16][36];    // per-warp P staging

    const int tid = threadIdx.x;
    const int lane = tid & 31;
    const int w = tid >> 5;
    const int g = lane >> 2;
    const int c = lane & 3;

    const int iq = gridDim.x - 1 - blockIdx.x;
    const int bh = blockIdx.y;
    const int row0 = iq * 128 + w * 16;
    const int rg = row0 + g;
    const int rg8 = rg + 8;

    const float* qb = qg + (size_t)bh * TSEQ * DH;
    const float* kb = kglob + (size_t)bh * TSEQ * DH;
    const float* vtb = vtg + (size_t)bh * DH * TSEQ;

    float qf[8][4];
#pragma unroll
    for (int kk = 0; kk < 8; kk++) {
        qf[kk][0] = to_tf32(qb[(size_t)rg * DH + kk * 8 + c] * 0.125f);
        qf[kk][1] = to_tf32(qb[(size_t)rg8 * DH + kk * 8 + c] * 0.125f);
        qf[kk][2] = to_tf32(qb[(size_t)rg * DH + kk * 8 + c + 4] * 0.125f);
        qf[kk][3] = to_tf32(qb[(size_t)rg8 * DH + kk * 8 + c + 4] * 0.125f);
    }

    float o[8][4];
#pragma unroll
    for (int nt = 0; nt < 8; nt++)
#pragma unroll
        for (int i = 0; i < 4; i++) o[nt][i] = 0.0f;
    float m0 = -1e30f, m1 = -1e30f, l0 = 0.0f, l1 = 0.0f;

    const int ntiles = 4 * iq + 4;
    for (int j = 0; j < ntiles; j++) {
        __syncthreads();
#pragma unroll
        for (int it = 0; it < 2; it++) {
            int idx = tid + it * 256;
            int r = idx >> 4, c4 = (idx & 15) * 4;
            float4 a = *(const float4*)(kb + (size_t)(j * 32 + r) * DH + c4);
            int kbase = (c4 & ~7) + ((c4 & 4) ? 1 : 0);
            Ks[r][kbase + 0] = to_tf32(a.x);
            Ks[r][kbase + 2] = to_tf32(a.y);
            Ks[r][kbase + 4] = to_tf32(a.z);
            Ks[r][kbase + 6] = to_tf32(a.w);
            int d = idx >> 3, k4 = (idx & 7) * 4;
            float4 b = *(const float4*)(vtb + (size_t)d * TSEQ + j * 32 + k4);
            int vbase = (k4 & ~7) + ((k4 & 4) ? 1 : 0);
            Vts[d][vbase + 0] = b.x;
            Vts[d][vbase + 2] = b.y;
            Vts[d][vbase + 4] = b.z;
            Vts[d][vbase + 6] = b.w;
        }
        __syncthreads();
        if (j * 32 > row0 + 15) continue;

        float s[4][4];
#pragma unroll
        for (int nt = 0; nt < 4; nt++)
#pragma unroll
            for (int i = 0; i < 4; i++) s[nt][i] = 0.0f;
#pragma unroll
        for (int kk = 0; kk < 8; kk++) {
#pragma unroll
            for (int nt = 0; nt < 4; nt++) {
                float2 bfr = *(float2*)&Ks[nt * 8 + g][kk * 8 + 2 * c];
                mma_tf32(s[nt], qf[kk], (const float*)&bfr);
            }
        }

        if (j >= 4 * iq) {
#pragma unroll
            for (int nt = 0; nt < 4; nt++) {
                int kg = j * 32 + nt * 8 + 2 * c;
                if (kg > rg)      s[nt][0] = -1e30f;
                if (kg + 1 > rg)  s[nt][1] = -1e30f;
                if (kg > rg8)     s[nt][2] = -1e30f;
                if (kg + 1 > rg8) s[nt][3] = -1e30f;
            }
        }

        float t0 = fmaxf(s[0][0], s[0][1]);
        float t1 = fmaxf(s[0][2], s[0][3]);
#pragma unroll
        for (int nt = 1; nt < 4; nt++) {
            t0 = fmaxf(t0, fmaxf(s[nt][0], s[nt][1]));
            t1 = fmaxf(t1, fmaxf(s[nt][2], s[nt][3]));
        }
        t0 = fmaxf(t0, __shfl_xor_sync(0xffffffffu, t0, 1));
        t0 = fmaxf(t0, __shfl_xor_sync(0xffffffffu, t0, 2));
        t1 = fmaxf(t1, __shfl_xor_sync(0xffffffffu, t1, 1));
        t1 = fmaxf(t1, __shfl_xor_sync(0xffffffffu, t1, 2));

        float mn0 = fmaxf(m0, t0), mn1 = fmaxf(m1, t1);
        float a0 = __expf(m0 - mn0), a1 = __expf(m1 - mn1);
        m0 = mn0; m1 = mn1;

        float rs0 = 0.0f, rs1 = 0.0f;
#pragma unroll
        for (int nt = 0; nt < 4; nt++) {
            s[nt][0] = __expf(s[nt][0] - m0);
            s[nt][1] = __expf(s[nt][1] - m0);
            s[nt][2] = __expf(s[nt][2] - m1);
            s[nt][3] = __expf(s[nt][3] - m1);
            rs0 += s[nt][0] + s[nt][1];
            rs1 += s[nt][2] + s[nt][3];
        }
        rs0 += __shfl_xor_sync(0xffffffffu, rs0, 1);
        rs0 += __shfl_xor_sync(0xffffffffu, rs0, 2);
        rs1 += __shfl_xor_sync(0xffffffffu, rs1, 1);
        rs1 += __shfl_xor_sync(0xffffffffu, rs1, 2);
        l0 = l0 * a0 + rs0;
        l1 = l1 * a1 + rs1;

#pragma unroll
        for (int nt = 0; nt < 8; nt++) {
            o[nt][0] *= a0; o[nt][1] *= a0;
            o[nt][2] *= a1; o[nt][3] *= a1;
        }

#pragma unroll
        for (int nt = 0; nt < 4; nt++) {
            *(float2*)&Ps[w][g][nt * 8 + 2 * c] =
                make_float2(to_tf32(s[nt][0]), to_tf32(s[nt][1]));
            *(float2*)&Ps[w][g + 8][nt * 8 + 2 * c] =
                make_float2(to_tf32(s[nt][2]), to_tf32(s[nt][3]));
        }
        __syncwarp();

#pragma unroll
        for (int kk = 0; kk < 4; kk++) {
            float af[4];
            af[0] = Ps[w][g][kk * 8 + c];
            af[1] = Ps[w][g + 8][kk * 8 + c];
            af[2] = Ps[w][g][kk * 8 + c + 4];
            af[3] = Ps[w][g + 8][kk * 8 + c + 4];
#pragma unroll
            for (int nt = 0; nt < 8; nt++) {
                float2 bfr = *(float2*)&Vts[nt * 8 + g][kk * 8 + 2 * c];
                mma_tf32(o[nt], af, (const float*)&bfr);
            }
        }
        __syncwarp();
    }

    // normalize + write to (B,T,C), k-permuted + rounded for the proj GEMM
    const int b = bh >> 4, h = bh & 15;
    const float i0 = 1.0f / l0, i1 = 1.0f / l1;
    float* y0 = yo + ((size_t)(b * TSEQ + rg) * CDIM + h * 64);
    float* y1 = yo + ((size_t)(b * TSEQ + rg8) * CDIM + h * 64);
    const int p0 = ((2 * c) & 3) * 2 + (((2 * c) & 4) ? 1 : 0);
    const int p1 = ((2 * c + 1) & 3) * 2 + (((2 * c + 1) & 4) ? 1 : 0);
#pragma unroll
    for (int nt = 0; nt < 8; nt++) {
        int base = nt * 8;
        y0[base + p0] = to_tf32(o[nt][0] * i0);
        y0[base + p1] = to_tf32(o[nt][1] * i0);
        y1[base + p0] = to_tf32(o[nt][2] * i1);
        y1[base + p1] = to_tf32(o[nt][3] * i1);
    }
}

// ---------------------------------------------------------------------------
extern "C" void kernel_launch(void* const* d_in, const int* in_sizes, int n_in,
                              void* d_out, int out_size) {
    const float* x  = (const float*)d_in[0];
    const float* wq = (const float*)d_in[1];
    const float* bq = (const float*)d_in[2];
    const float* wk = (const float*)d_in[3];
    const float* bk = (const float*)d_in[4];
    const float* wv = (const float*)d_in[5];
    const float* bv = (const float*)d_in[6];
    const float* wp = (const float*)d_in[7];
    const float* bp = (const float*)d_in[8];

    float* out  = (float*)d_out;
    float* kout = out + (size_t)BSZ * TSEQ * CDIM;       // present[0] (k)
    float* vout = kout + (size_t)BSZ * HN * TSEQ * DH;   // present[1] (v)

    perm_x<<<BSZ * TSEQ, 256>>>(x);
    transpose_w<<<dim3(32, 32, 4), dim3(32, 8)>>>(wq, wk, wv, wp);

    dim3 gg(8, 128);   // N/128, M/64
    gemm_cp<0, 2><<<gg, 128>>>(bq, nullptr, 0);   // q -> g_q
    gemm_cp<0, 1><<<gg, 128>>>(bk, kout, 1);      // k -> present[0]
    gemm_cp<0, 1><<<gg, 128>>>(bv, vout, 2);      // v -> present[1]

    transpose_v<<<dim3(TSEQ / 32, DH / 32, BSZ * HN), dim3(32, 8)>>>(vout);

    attn_tc<<<dim3(TSEQ / 128, BSZ * HN), 256>>>(kout);

    gemm_cp<1, 0><<<gg, 128>>>(bp, out, 3);       // y = att @ wp + bp
}